// round 15
// baseline (speedup 1.0000x reference)
#include <cuda_runtime.h>

#define EPSB 1e-5f
#define NB 16

// ---------------- device-global scratch (no allocation allowed) ----------------
__device__ __align__(128) unsigned char g_actA[NB * 160 * 320 * 16]; // 13.1 MB
__device__ __align__(128) unsigned char g_actB[NB * 80 * 160 * 32];  //  6.6 MB

// packed int8x4 quantized weights, layout per weight: [tap][cin4][cout]
__device__ int   g_wq[52560];
__device__ float g_sw[9];
__device__ float g_A[512];
__device__ float g_B[512];
__device__ float g_head_sc;

// ---------------- prep kernels ----------------
struct MaxArgs { const float* p[9]; int n[9]; };

__global__ void k_maxabs(MaxArgs a) {
    __shared__ float red[8];
    const int b = blockIdx.x;
    const float* __restrict__ w = a.p[b];
    const int n = a.n[b];
    float m = 0.f;
    for (int i = threadIdx.x; i < n; i += blockDim.x) m = fmaxf(m, fabsf(w[i]));
    for (int s = 16; s; s >>= 1) m = fmaxf(m, __shfl_xor_sync(0xffffffffu, m, s));
    if ((threadIdx.x & 31) == 0) red[threadIdx.x >> 5] = m;
    __syncthreads();
    if (threadIdx.x < 32) {
        float v = (threadIdx.x < 8) ? red[threadIdx.x] : 0.f;
        for (int s = 4; s; s >>= 1) v = fmaxf(v, __shfl_xor_sync(0xffffffffu, v, s));
        if (threadIdx.x == 0) g_sw[b] = v / 7.0f;
    }
}

struct PackArgs { const float* w[9]; };

__global__ void k_pack(PackArgs a) {
    const int off[10]  = {0, 144, 1296, 5904, 15120, 24336, 33552, 42768, 51984, 52560};
    const int cinR[9]  = {3, 16, 32, 64, 64, 64, 64, 64, 64};
    const int cin4[9]  = {1, 4, 8, 16, 16, 16, 16, 16, 16};
    const int coutA[9] = {16, 32, 64, 64, 64, 64, 64, 64, 36};
    const int kk[9]    = {3, 3, 3, 3, 3, 3, 3, 3, 1};

    int idx = blockIdx.x * blockDim.x + threadIdx.x;
    if (idx >= 52560) return;
    int wi = 0;
    while (wi < 8 && idx >= off[wi + 1]) wi++;
    const int local = idx - off[wi];
    const int C4 = cin4[wi], CO = coutA[wi], K = kk[wi], CR = cinR[wi];
    const int tap = local / (C4 * CO);
    const int rest = local % (C4 * CO);
    const int c4 = rest / CO, o = rest % CO;
    const int ky = tap / K, kx = tap % K;
    const float s = g_sw[wi];
    const float* __restrict__ w = a.w[wi];
    unsigned packed = 0;
#pragma unroll
    for (int j = 0; j < 4; j++) {
        const int ci = c4 * 4 + j;
        int q = 0;
        if (ci < CR) {
            float v = w[((o * CR + ci) * K + ky) * K + kx];
            q = __float2int_rn(__fdiv_rn(v, s));
            q = min(7, max(-7, q));
        }
        packed |= (unsigned)(q & 255) << (j * 8);
    }
    g_wq[idx] = (int)packed;
}

struct BnArgs { const float* bn[8]; const float* scales; };

__global__ void k_params(BnArgs a) {
    const int couts[8] = {16, 32, 64, 64, 64, 64, 64, 64};
    for (int idx = threadIdx.x; idx < 8 * 64; idx += blockDim.x) {
        const int blk = idx >> 6, c = idx & 63;
        const int C = couts[blk];
        if (c >= C) continue;
        const float* __restrict__ bn = a.bn[blk];
        const float g = bn[c], b = bn[C + c], m = bn[2 * C + c], v = bn[3 * C + c];
        const float inv = __fdiv_rn(g, sqrtf(v + EPSB));
        const float s_in = a.scales[1 + blk];
        const float s_relu = a.scales[10 + blk];
        const float sw = g_sw[blk];
        g_A[idx] = __fdiv_rn(sw * s_in * inv, s_relu);
        g_B[idx] = __fdiv_rn(b - m * inv, s_relu);
    }
    if (threadIdx.x == 0) g_head_sc = g_sw[8] * a.scales[9];
}

// ---------------- dp4a conv (b0, b1) — unchanged from R14 passing kernel ----------------
template <int CIN4, int COUT, bool POOL, int CHG, bool FIRST, int MINB>
__global__ __launch_bounds__(256, MINB) void
k_conv(const float* __restrict__ xin, int inSel, int outSel, int woff,
       const float* __restrict__ scales, int sRelu, int sNext, int blk, int H, int W)
{
    constexpr int NQ   = 256 / CHG;
    constexpr int CO   = COUT / CHG;
    constexpr int TH   = (NQ / 8) * 2;
    constexpr int HR   = TH + 2;
    constexpr int CIN  = CIN4 * 4;
    constexpr int XS   = CIN4 | 1;
    constexpr int NW   = 9 * CIN4 * COUT;

    extern __shared__ int smem[];
    int*   sw_   = smem;
    int*   sx    = smem + NW;
    float* sA    = (float*)(sx + HR * 18 * XS);
    float* sB    = sA + COUT;
    int*   slut  = (int*)(sB + COUT);
    int*   lut01 = slut + 16;

    const unsigned char* __restrict__ in  = inSel ? g_actB : g_actA;
    unsigned char*       __restrict__ out = outSel ? g_actB : g_actA;

    const int tid = threadIdx.x;
    if (tid < 16) {
        const float sp = scales[sRelu], sc = scales[sNext];
        int v = __float2int_rn(__fdiv_rn((float)tid * sp, sc));
        slut[tid] = min(7, max(-8, v)) & 255;
        if (FIRST) {
            int u = __float2int_rn(__fdiv_rn((float)(tid - 8) * scales[0], scales[1]));
            lut01[tid] = min(7, max(-8, u)) & 255;
        }
    }
    if (tid < COUT) { sA[tid] = g_A[blk * 64 + tid]; sB[tid] = g_B[blk * 64 + tid]; }
    {
        const int4* __restrict__ wq4 = reinterpret_cast<const int4*>(g_wq + woff);
        int4* sw4 = reinterpret_cast<int4*>(sw_);
        for (int i = tid; i < NW / 4; i += 256) sw4[i] = wq4[i];
    }

    const int b  = blockIdx.z;
    const int x0 = blockIdx.x * 16, y0 = blockIdx.y * TH;

    if constexpr (FIRST) {
        __syncthreads();                    // halo below reads lut01 (smem)
        const float r0 = __frcp_rn(__ldg(&scales[0]));
        for (int i = tid; i < HR * 18; i += 256) {
            const int ty = i / 18, tx = i % 18;
            const int iy = y0 + ty - 1, ix = x0 + tx - 1;
            unsigned pkd = 0;
            if (iy >= 0 && iy < H && ix >= 0 && ix < W) {
                const size_t base = (size_t)b * 3 * H * W + (size_t)iy * W + ix;
#pragma unroll
                for (int c = 0; c < 3; c++) {
                    const float f = xin[base + (size_t)c * H * W];
                    int q0 = __float2int_rn(f * r0);
                    q0 = min(7, max(-8, q0));
                    pkd |= (unsigned)lut01[q0 + 8] << (8 * c);
                }
            }
            sx[i * XS] = (int)pkd;
        }
    } else if constexpr (CIN4 >= 4) {
        constexpr int NC16 = CIN4 / 4;
        for (int i = tid; i < HR * 18 * NC16; i += 256) {
            const int pix = i / NC16, c16 = i % NC16;
            const int ty = pix / 18, tx = pix % 18;
            const int iy = y0 + ty - 1, ix = x0 + tx - 1;
            uint4 v = make_uint4(0, 0, 0, 0);
            if (iy >= 0 && iy < H && ix >= 0 && ix < W)
                v = *reinterpret_cast<const uint4*>(
                    in + ((size_t)(b * H + iy) * W + ix) * CIN + c16 * 16);
            int* d = sx + pix * XS + c16 * 4;
            d[0] = (int)v.x; d[1] = (int)v.y; d[2] = (int)v.z; d[3] = (int)v.w;
        }
    } else {
        for (int i = tid; i < HR * 18; i += 256) {
            const int ty = i / 18, tx = i % 18;
            const int iy = y0 + ty - 1, ix = x0 + tx - 1;
            int v = 0;
            if (iy >= 0 && iy < H && ix >= 0 && ix < W)
                v = *reinterpret_cast<const int*>(
                    in + ((size_t)(b * H + iy) * W + ix) * 4);
            sx[i * XS] = v;
        }
    }
    __syncthreads();

    const int chgrp = tid / NQ, q = tid % NQ;
    const int chbase = chgrp * CO;
    const int px0 = (q & 7) * 2, py0 = (q >> 3) * 2;

    int acc[4][CO];
#pragma unroll
    for (int p = 0; p < 4; p++)
#pragma unroll
    for (int o = 0; o < CO; o++) acc[p][o] = 0;

    for (int c4 = 0; c4 < CIN4; c4++) {
        int win[16];
#pragma unroll
        for (int r = 0; r < 4; r++)
#pragma unroll
        for (int c = 0; c < 4; c++)
            win[r * 4 + c] = sx[((py0 + r) * 18 + px0 + c) * XS + c4];

#pragma unroll
        for (int ky = 0; ky < 3; ky++)
#pragma unroll
        for (int kx = 0; kx < 3; kx++) {
            const int* __restrict__ w = sw_ + ((ky * 3 + kx) * CIN4 + c4) * COUT + chbase;
#pragma unroll
            for (int j = 0; j < CO; j += 4) {
                const int4 w4 = *reinterpret_cast<const int4*>(w + j);
#pragma unroll
                for (int p = 0; p < 4; p++) {
                    const int xw = win[((p >> 1) + ky) * 4 + (p & 1) + kx];
                    acc[p][j + 0] = __dp4a(xw, w4.x, acc[p][j + 0]);
                    acc[p][j + 1] = __dp4a(xw, w4.y, acc[p][j + 1]);
                    acc[p][j + 2] = __dp4a(xw, w4.z, acc[p][j + 2]);
                    acc[p][j + 3] = __dp4a(xw, w4.w, acc[p][j + 3]);
                }
            }
        }
    }

    if (POOL) {
        const int gy = y0 + py0, gx = x0 + px0;
        if (gy < H && gx < W) {
            unsigned pk[CO / 4];
#pragma unroll
            for (int j = 0; j < CO / 4; j++) pk[j] = 0;
#pragma unroll
            for (int o = 0; o < CO; o++) {
                const int m = max(max(acc[0][o], acc[1][o]), max(acc[2][o], acc[3][o]));
                const float y = fmaf((float)m, sA[chbase + o], sB[chbase + o]);
                int qq = __float2int_rn(y);
                qq = min(15, max(0, qq));
                pk[o >> 2] |= (unsigned)slut[qq] << ((o & 3) * 8);
            }
            unsigned char* dst = out
                + ((size_t)(b * (H >> 1) + (gy >> 1)) * (W >> 1) + (gx >> 1)) * COUT + chbase;
            if constexpr (CO == 16)
                *reinterpret_cast<uint4*>(dst) = make_uint4(pk[0], pk[1], pk[2], pk[3]);
            else if constexpr (CO == 8)
                *reinterpret_cast<uint2*>(dst) = make_uint2(pk[0], pk[1]);
            else
                *reinterpret_cast<unsigned*>(dst) = pk[0];
        }
    } else {
#pragma unroll
        for (int p = 0; p < 4; p++) {
            const int gy = y0 + py0 + (p >> 1), gx = x0 + px0 + (p & 1);
            if (gy < H && gx < W) {
                unsigned pk[CO / 4];
#pragma unroll
                for (int j = 0; j < CO / 4; j++) pk[j] = 0;
#pragma unroll
                for (int o = 0; o < CO; o++) {
                    const float y = fmaf((float)acc[p][o], sA[chbase + o], sB[chbase + o]);
                    int qq = __float2int_rn(y);
                    qq = min(15, max(0, qq));
                    pk[o >> 2] |= (unsigned)slut[qq] << ((o & 3) * 8);
                }
                unsigned char* dst = out + ((size_t)(b * H + gy) * W + gx) * COUT + chbase;
                if constexpr (CO == 16)
                    *reinterpret_cast<uint4*>(dst) = make_uint4(pk[0], pk[1], pk[2], pk[3]);
                else if constexpr (CO == 8)
                    *reinterpret_cast<uint2*>(dst) = make_uint2(pk[0], pk[1]);
                else
                    *reinterpret_cast<unsigned*>(dst) = pk[0];
            }
        }
    }
}

// ---------------- tensor-core conv (b2..b7): mma.sync m16n8k32 s8 ----------------
// CTA = 8 warps over a 16x16 pixel tile; warp w owns image rows {2w, 2w+1} x 16
// pixels x all 64 couts. Implicit GEMM: per (tap, kchunk) the A fragment rows are
// pixels (direct LDS.32 from the NHWC tile; XS chosen so the 8x4 lane access
// pattern is bank-conflict-free) and B fragments are packed weight words
// ([tap][c4][cout]; broadcast across lane quads). K = 9*CIN via 9*KC mma steps
// per n-tile; 8 n-tiles cover COUT=64. Pool: vertical max in-lane (2 rows),
// horizontal max via shfl_xor(4) (rows r,r^1 of the M tile are pixel pairs).
// Epilogue identical float math; bytes staged in per-warp smem, stored uint4.
#define MMA_S8(c, a0, a1, a2, a3, b0, b1)                                   \
    asm volatile("mma.sync.aligned.m16n8k32.row.col.s32.s8.s8.s32 "         \
                 "{%0,%1,%2,%3},{%4,%5,%6,%7},{%8,%9},{%0,%1,%2,%3};"       \
                 : "+r"((c)[0]), "+r"((c)[1]), "+r"((c)[2]), "+r"((c)[3])   \
                 : "r"(a0), "r"(a1), "r"(a2), "r"(a3), "r"(b0), "r"(b1))

template <int CIN4, bool POOL>
__global__ __launch_bounds__(256, 2) void
k_conv_mma(int inSel, int outSel, int woff, const float* __restrict__ scales,
           int sRelu, int sNext, int blk, int H, int W)
{
    constexpr int KC  = CIN4 / 8;            // k32 chunks per tap
    constexpr int XS  = (CIN4 == 16) ? 20 : 12; // pixel stride (words), conflict-free
    constexpr int CIN = CIN4 * 4;
    constexpr int NW  = 9 * CIN4 * 64;
    constexpr int STAGE = POOL ? 512 : 2048; // per-warp staging bytes

    extern __shared__ int smem[];
    int*   sw_  = smem;                      // weights [tap][c4][cout]
    int*   sx   = smem + NW;                 // 18x18 halo tile
    float* sA   = (float*)(sx + 324 * XS);
    float* sB   = sA + 64;
    int*   slut = (int*)(sB + 64);
    unsigned char* stage_all = (unsigned char*)(slut + 16);

    const unsigned char* __restrict__ in  = inSel ? g_actB : g_actA;
    unsigned char*       __restrict__ out = outSel ? g_actB : g_actA;

    const int tid = threadIdx.x;
    if (tid < 16) {
        const float sp = scales[sRelu], sc = scales[sNext];
        int v = __float2int_rn(__fdiv_rn((float)tid * sp, sc));
        slut[tid] = min(7, max(-8, v)) & 255;
    }
    if (tid < 64) { sA[tid] = g_A[blk * 64 + tid]; sB[tid] = g_B[blk * 64 + tid]; }
    {
        const int4* __restrict__ wq4 = reinterpret_cast<const int4*>(g_wq + woff);
        int4* sw4 = reinterpret_cast<int4*>(sw_);
        for (int i = tid; i < NW / 4; i += 256) sw4[i] = wq4[i];
    }

    const int b  = blockIdx.z;
    const int x0 = blockIdx.x * 16, y0 = blockIdx.y * 16;

    {   // halo load (zero-filled OOB)
        constexpr int NC16 = CIN4 / 4;
        for (int i = tid; i < 324 * NC16; i += 256) {
            const int pix = i / NC16, c16 = i % NC16;
            const int ty = pix / 18, tx = pix % 18;
            const int iy = y0 + ty - 1, ix = x0 + tx - 1;
            uint4 v = make_uint4(0, 0, 0, 0);
            if (iy >= 0 && iy < H && ix >= 0 && ix < W)
                v = *reinterpret_cast<const uint4*>(
                    in + ((size_t)(b * H + iy) * W + ix) * CIN + c16 * 16);
            int* d = sx + pix * XS + c16 * 4;
            d[0] = (int)v.x; d[1] = (int)v.y; d[2] = (int)v.z; d[3] = (int)v.w;
        }
    }
    __syncthreads();

    const int wid = tid >> 5, lane = tid & 31;
    const int l4 = lane >> 2, lq = lane & 3;
    const int t0 = wid * 2;                  // warp's first tile row

    int C[2][8][4];
#pragma unroll
    for (int r = 0; r < 2; r++)
#pragma unroll
    for (int nt = 0; nt < 8; nt++)
#pragma unroll
    for (int j = 0; j < 4; j++) C[r][nt][j] = 0;

    const int pA = (t0 * 18 + l4) * XS + lq; // A base: row t0+ky, pixel l4+kx, c4=lq
    const int pB = lq * 64 + l4;             // B base: c4=lq(+4), cout=n0+l4

#pragma unroll
    for (int ky = 0; ky < 3; ky++)
#pragma unroll
    for (int kx = 0; kx < 3; kx++)
#pragma unroll
    for (int kc = 0; kc < KC; kc++) {
        const int ao = pA + (ky * 18 + kx) * XS + kc * 8;
        // A frag (row-major 16x32): a0=(g,klo) a1=(g+8,klo) a2=(g,khi) a3=(g+8,khi)
        const int a00 = sx[ao];
        const int a01 = sx[ao + 8 * XS];
        const int a02 = sx[ao + 4];
        const int a03 = sx[ao + 8 * XS + 4];
        const int a10 = sx[ao + 18 * XS];
        const int a11 = sx[ao + 26 * XS];
        const int a12 = sx[ao + 18 * XS + 4];
        const int a13 = sx[ao + 26 * XS + 4];
        const int bo = pB + ((ky * 3 + kx) * CIN4 + kc * 8) * 64;
#pragma unroll
        for (int nt = 0; nt < 8; nt++) {
            const int b0 = sw_[bo + nt * 8];
            const int b1 = sw_[bo + nt * 8 + 256];   // c4 + 4
            MMA_S8(C[0][nt], a00, a01, a02, a03, b0, b1);
            MMA_S8(C[1][nt], a10, a11, a12, a13, b0, b1);
        }
    }

    unsigned char* stage = stage_all + wid * STAGE;

    if (POOL) {
#pragma unroll
        for (int nt = 0; nt < 8; nt++) {
            int m0 = max(C[0][nt][0], C[1][nt][0]);
            int m1 = max(C[0][nt][1], C[1][nt][1]);
            int m2 = max(C[0][nt][2], C[1][nt][2]);
            int m3 = max(C[0][nt][3], C[1][nt][3]);
            m0 = max(m0, __shfl_xor_sync(0xffffffffu, m0, 4));
            m1 = max(m1, __shfl_xor_sync(0xffffffffu, m1, 4));
            m2 = max(m2, __shfl_xor_sync(0xffffffffu, m2, 4));
            m3 = max(m3, __shfl_xor_sync(0xffffffffu, m3, 4));
            if ((l4 & 1) == 0) {
                const int co = nt * 8 + lq * 2;
                int q0 = __float2int_rn(fmaf((float)m0, sA[co], sB[co]));
                int q1 = __float2int_rn(fmaf((float)m1, sA[co + 1], sB[co + 1]));
                int q2 = __float2int_rn(fmaf((float)m2, sA[co], sB[co]));
                int q3 = __float2int_rn(fmaf((float)m3, sA[co + 1], sB[co + 1]));
                q0 = min(15, max(0, q0)); q1 = min(15, max(0, q1));
                q2 = min(15, max(0, q2)); q3 = min(15, max(0, q3));
                *(unsigned short*)(stage + (l4 >> 1) * 64 + co) =
                    (unsigned short)(slut[q0] | (slut[q1] << 8));
                *(unsigned short*)(stage + (4 + (l4 >> 1)) * 64 + co) =
                    (unsigned short)(slut[q2] | (slut[q3] << 8));
            }
        }
        __syncwarp();
        const int Ho = H >> 1, Wo = W >> 1;
        const int oy = (y0 >> 1) + wid;
        const int ox = (x0 >> 1) + l4;
        if (oy < Ho && ox < Wo) {
            const uint4 v = *(const uint4*)(stage + l4 * 64 + lq * 16);
            *(uint4*)(out + ((size_t)(b * Ho + oy) * Wo + ox) * 64 + lq * 16) = v;
        }
    } else {
#pragma unroll
        for (int nt = 0; nt < 8; nt++) {
            const int co = nt * 8 + lq * 2;
#pragma unroll
            for (int r = 0; r < 2; r++) {
                int q0 = __float2int_rn(fmaf((float)C[r][nt][0], sA[co], sB[co]));
                int q1 = __float2int_rn(fmaf((float)C[r][nt][1], sA[co + 1], sB[co + 1]));
                int q2 = __float2int_rn(fmaf((float)C[r][nt][2], sA[co], sB[co]));
                int q3 = __float2int_rn(fmaf((float)C[r][nt][3], sA[co + 1], sB[co + 1]));
                q0 = min(15, max(0, q0)); q1 = min(15, max(0, q1));
                q2 = min(15, max(0, q2)); q3 = min(15, max(0, q3));
                *(unsigned short*)(stage + (r * 16 + l4) * 64 + co) =
                    (unsigned short)(slut[q0] | (slut[q1] << 8));
                *(unsigned short*)(stage + (r * 16 + l4 + 8) * 64 + co) =
                    (unsigned short)(slut[q2] | (slut[q3] << 8));
            }
        }
        __syncwarp();
#pragma unroll
        for (int j = 0; j < 4; j++) {
            const int idx = j * 32 + lane;
            const int p = idx >> 2, ch = idx & 3;
            const int r = p >> 4, px = p & 15;
            const int gy = y0 + t0 + r, gx = x0 + px;
            if (gy < H && gx < W) {
                const uint4 v = *(const uint4*)(stage + p * 64 + ch * 16);
                *(uint4*)(out + ((size_t)(b * H + gy) * W + gx) * 64 + ch * 16) = v;
            }
        }
    }
}

// ---------------- head: 1x1 conv (64->36) + bias, fp32 NCHW out ----------------
__global__ __launch_bounds__(256) void
k_head(float* __restrict__ outp, const float* __restrict__ b9)
{
    __shared__ int   sw_[576];
    __shared__ float s_sc;
    const int tid = threadIdx.x;
    if (tid == 0) s_sc = g_head_sc;
    for (int i = tid; i < 576; i += 256) sw_[i] = g_wq[51984 + i];
    __syncthreads();

    const int p = blockIdx.x * 256 + tid;
    if (p >= 12800) return;
    const int b = p / 800, rem = p % 800;
    const int4* __restrict__ src = reinterpret_cast<const int4*>(g_actB + (size_t)p * 64);

    int xw[16];
#pragma unroll
    for (int j = 0; j < 4; j++) {
        const int4 v = src[j];
        xw[4 * j + 0] = v.x; xw[4 * j + 1] = v.y; xw[4 * j + 2] = v.z; xw[4 * j + 3] = v.w;
    }
    int acc[36];
#pragma unroll
    for (int o = 0; o < 36; o++) acc[o] = 0;
#pragma unroll
    for (int c4 = 0; c4 < 16; c4++) {
        const int x = xw[c4];
        const int* __restrict__ w = sw_ + c4 * 36;
#pragma unroll
        for (int o = 0; o < 36; o++) acc[o] = __dp4a(x, w[o], acc[o]);
    }
    const float sc = s_sc;
#pragma unroll
    for (int o = 0; o < 36; o++)
        outp[(size_t)(b * 36 + o) * 800 + rem] = (float)acc[o] * sc + __ldg(&b9[o]);
}

// ---------------- launch ----------------
extern "C" void kernel_launch(void* const* d_in, const int* in_sizes, int n_in,
                              void* d_out, int out_size)
{
    const float* x      = (const float*)d_in[0];
    const float* b9     = (const float*)d_in[10];
    const float* scales = (const float*)d_in[19];

    const int wn[9] = {432, 4608, 18432, 36864, 36864, 36864, 36864, 36864, 2304};

    MaxArgs ma;
    for (int i = 0; i < 9; i++) { ma.p[i] = (const float*)d_in[1 + i]; ma.n[i] = wn[i]; }
    k_maxabs<<<9, 256>>>(ma);

    PackArgs pa;
    for (int i = 0; i < 9; i++) pa.w[i] = (const float*)d_in[1 + i];
    k_pack<<<(52560 + 255) / 256, 256>>>(pa);

    BnArgs ba;
    for (int i = 0; i < 8; i++) ba.bn[i] = (const float*)d_in[11 + i];
    ba.scales = scales;
    k_params<<<1, 256>>>(ba);

    // >48KB dynamic smem (idempotent, capture-safe host calls)
    cudaFuncSetAttribute(k_conv_mma<16, true >, cudaFuncAttributeMaxDynamicSharedMemorySize, 67456);
    cudaFuncSetAttribute(k_conv_mma<16, false>, cudaFuncAttributeMaxDynamicSharedMemorySize, 79744);

    //                                  grid                 smem       in out  woff           sRelu sNext blk  H    W
    k_conv<1, 16, true, 2, true, 4><<<dim3(40, 10, 16), 256,  3280>>>(x, 0, 0,     0, scales, 10, 2, 0, 320, 640);
    k_conv<4, 32, true, 4, false,4><<<dim3(20, 10, 16), 256, 11472>>>(x, 0, 1,   144, scales, 11, 3, 1, 160, 320);
    k_conv_mma<8,  true ><<<dim3(10, 5, 16), 256, 38656>>>(1, 0,  1296, scales, 12, 4, 2,  80, 160);
    k_conv_mma<16, true ><<<dim3( 5, 3, 16), 256, 67456>>>(0, 1,  5904, scales, 13, 5, 3,  40,  80);
    k_conv_mma<16, false><<<dim3( 3, 2, 16), 256, 79744>>>(1, 0, 15120, scales, 14, 6, 4,  20,  40);
    k_conv_mma<16, false><<<dim3( 3, 2, 16), 256, 79744>>>(0, 1, 24336, scales, 15, 7, 5,  20,  40);
    k_conv_mma<16, false><<<dim3( 3, 2, 16), 256, 79744>>>(1, 0, 33552, scales, 16, 8, 6,  20,  40);
    k_conv_mma<16, false><<<dim3( 3, 2, 16), 256, 79744>>>(0, 1, 42768, scales, 17, 9, 7,  20,  40);
    k_head<<<50, 256>>>((float*)d_out, b9);
}

// round 16
// speedup vs baseline: 1.1385x; 1.1385x over previous
#include <cuda_runtime.h>

#define EPSB 1e-5f
#define NB 16

// ---------------- device-global scratch (no allocation allowed) ----------------
__device__ __align__(128) unsigned char g_actA[NB * 160 * 320 * 16]; // 13.1 MB
__device__ __align__(128) unsigned char g_actB[NB * 80 * 160 * 32];  //  6.6 MB

// packed int8x4 quantized weights, layout per weight: [tap][cin4][cout]
__device__ int   g_wq[52560];
__device__ float g_sw[9];
__device__ float g_A[512];
__device__ float g_B[512];
__device__ float g_head_sc;

// ---------------- prep kernels ----------------
struct MaxArgs { const float* p[9]; int n[9]; };

__global__ void k_maxabs(MaxArgs a) {
    __shared__ float red[8];
    const int b = blockIdx.x;
    const float* __restrict__ w = a.p[b];
    const int n = a.n[b];
    float m = 0.f;
    for (int i = threadIdx.x; i < n; i += blockDim.x) m = fmaxf(m, fabsf(w[i]));
    for (int s = 16; s; s >>= 1) m = fmaxf(m, __shfl_xor_sync(0xffffffffu, m, s));
    if ((threadIdx.x & 31) == 0) red[threadIdx.x >> 5] = m;
    __syncthreads();
    if (threadIdx.x < 32) {
        float v = (threadIdx.x < 8) ? red[threadIdx.x] : 0.f;
        for (int s = 4; s; s >>= 1) v = fmaxf(v, __shfl_xor_sync(0xffffffffu, v, s));
        if (threadIdx.x == 0) g_sw[b] = v / 7.0f;
    }
}

struct PackArgs { const float* w[9]; };

__global__ void k_pack(PackArgs a) {
    const int off[10]  = {0, 144, 1296, 5904, 15120, 24336, 33552, 42768, 51984, 52560};
    const int cinR[9]  = {3, 16, 32, 64, 64, 64, 64, 64, 64};
    const int cin4[9]  = {1, 4, 8, 16, 16, 16, 16, 16, 16};
    const int coutA[9] = {16, 32, 64, 64, 64, 64, 64, 64, 36};
    const int kk[9]    = {3, 3, 3, 3, 3, 3, 3, 3, 1};

    int idx = blockIdx.x * blockDim.x + threadIdx.x;
    if (idx >= 52560) return;
    int wi = 0;
    while (wi < 8 && idx >= off[wi + 1]) wi++;
    const int local = idx - off[wi];
    const int C4 = cin4[wi], CO = coutA[wi], K = kk[wi], CR = cinR[wi];
    const int tap = local / (C4 * CO);
    const int rest = local % (C4 * CO);
    const int c4 = rest / CO, o = rest % CO;
    const int ky = tap / K, kx = tap % K;
    const float s = g_sw[wi];
    const float* __restrict__ w = a.w[wi];
    unsigned packed = 0;
#pragma unroll
    for (int j = 0; j < 4; j++) {
        const int ci = c4 * 4 + j;
        int q = 0;
        if (ci < CR) {
            float v = w[((o * CR + ci) * K + ky) * K + kx];
            q = __float2int_rn(__fdiv_rn(v, s));
            q = min(7, max(-7, q));
        }
        packed |= (unsigned)(q & 255) << (j * 8);
    }
    g_wq[idx] = (int)packed;
}

struct BnArgs { const float* bn[8]; const float* scales; };

__global__ void k_params(BnArgs a) {
    const int couts[8] = {16, 32, 64, 64, 64, 64, 64, 64};
    for (int idx = threadIdx.x; idx < 8 * 64; idx += blockDim.x) {
        const int blk = idx >> 6, c = idx & 63;
        const int C = couts[blk];
        if (c >= C) continue;
        const float* __restrict__ bn = a.bn[blk];
        const float g = bn[c], b = bn[C + c], m = bn[2 * C + c], v = bn[3 * C + c];
        const float inv = __fdiv_rn(g, sqrtf(v + EPSB));
        const float s_in = a.scales[1 + blk];
        const float s_relu = a.scales[10 + blk];
        const float sw = g_sw[blk];
        g_A[idx] = __fdiv_rn(sw * s_in * inv, s_relu);
        g_B[idx] = __fdiv_rn(b - m * inv, s_relu);
    }
    if (threadIdx.x == 0) g_head_sc = g_sw[8] * a.scales[9];
}

// ---------------- dp4a conv (b0, b1, b4..b7) — R14 passing version ----------------
template <int CIN4, int COUT, bool POOL, int CHG, bool FIRST, int MINB>
__global__ __launch_bounds__(256, MINB) void
k_conv(const float* __restrict__ xin, int inSel, int outSel, int woff,
       const float* __restrict__ scales, int sRelu, int sNext, int blk, int H, int W)
{
    constexpr int NQ   = 256 / CHG;
    constexpr int CO   = COUT / CHG;
    constexpr int TH   = (NQ / 8) * 2;
    constexpr int HR   = TH + 2;
    constexpr int CIN  = CIN4 * 4;
    constexpr int XS   = CIN4 | 1;
    constexpr int NW   = 9 * CIN4 * COUT;

    extern __shared__ int smem[];
    int*   sw_   = smem;
    int*   sx    = smem + NW;
    float* sA    = (float*)(sx + HR * 18 * XS);
    float* sB    = sA + COUT;
    int*   slut  = (int*)(sB + COUT);
    int*   lut01 = slut + 16;

    const unsigned char* __restrict__ in  = inSel ? g_actB : g_actA;
    unsigned char*       __restrict__ out = outSel ? g_actB : g_actA;

    const int tid = threadIdx.x;
    if (tid < 16) {
        const float sp = scales[sRelu], sc = scales[sNext];
        int v = __float2int_rn(__fdiv_rn((float)tid * sp, sc));
        slut[tid] = min(7, max(-8, v)) & 255;
        if (FIRST) {
            int u = __float2int_rn(__fdiv_rn((float)(tid - 8) * scales[0], scales[1]));
            lut01[tid] = min(7, max(-8, u)) & 255;
        }
    }
    if (tid < COUT) { sA[tid] = g_A[blk * 64 + tid]; sB[tid] = g_B[blk * 64 + tid]; }
    {
        const int4* __restrict__ wq4 = reinterpret_cast<const int4*>(g_wq + woff);
        int4* sw4 = reinterpret_cast<int4*>(sw_);
        for (int i = tid; i < NW / 4; i += 256) sw4[i] = wq4[i];
    }

    const int b  = blockIdx.z;
    const int x0 = blockIdx.x * 16, y0 = blockIdx.y * TH;

    if constexpr (FIRST) {
        __syncthreads();                    // halo below reads lut01 (smem)
        const float r0 = __frcp_rn(__ldg(&scales[0]));
        for (int i = tid; i < HR * 18; i += 256) {
            const int ty = i / 18, tx = i % 18;
            const int iy = y0 + ty - 1, ix = x0 + tx - 1;
            unsigned pkd = 0;
            if (iy >= 0 && iy < H && ix >= 0 && ix < W) {
                const size_t base = (size_t)b * 3 * H * W + (size_t)iy * W + ix;
#pragma unroll
                for (int c = 0; c < 3; c++) {
                    const float f = xin[base + (size_t)c * H * W];
                    int q0 = __float2int_rn(f * r0);
                    q0 = min(7, max(-8, q0));
                    pkd |= (unsigned)lut01[q0 + 8] << (8 * c);
                }
            }
            sx[i * XS] = (int)pkd;
        }
    } else if constexpr (CIN4 >= 4) {
        constexpr int NC16 = CIN4 / 4;
        for (int i = tid; i < HR * 18 * NC16; i += 256) {
            const int pix = i / NC16, c16 = i % NC16;
            const int ty = pix / 18, tx = pix % 18;
            const int iy = y0 + ty - 1, ix = x0 + tx - 1;
            uint4 v = make_uint4(0, 0, 0, 0);
            if (iy >= 0 && iy < H && ix >= 0 && ix < W)
                v = *reinterpret_cast<const uint4*>(
                    in + ((size_t)(b * H + iy) * W + ix) * CIN + c16 * 16);
            int* d = sx + pix * XS + c16 * 4;
            d[0] = (int)v.x; d[1] = (int)v.y; d[2] = (int)v.z; d[3] = (int)v.w;
        }
    } else {
        for (int i = tid; i < HR * 18; i += 256) {
            const int ty = i / 18, tx = i % 18;
            const int iy = y0 + ty - 1, ix = x0 + tx - 1;
            int v = 0;
            if (iy >= 0 && iy < H && ix >= 0 && ix < W)
                v = *reinterpret_cast<const int*>(
                    in + ((size_t)(b * H + iy) * W + ix) * 4);
            sx[i * XS] = v;
        }
    }
    __syncthreads();

    const int chgrp = tid / NQ, q = tid % NQ;
    const int chbase = chgrp * CO;
    const int px0 = (q & 7) * 2, py0 = (q >> 3) * 2;

    int acc[4][CO];
#pragma unroll
    for (int p = 0; p < 4; p++)
#pragma unroll
    for (int o = 0; o < CO; o++) acc[p][o] = 0;

    for (int c4 = 0; c4 < CIN4; c4++) {
        int win[16];
#pragma unroll
        for (int r = 0; r < 4; r++)
#pragma unroll
        for (int c = 0; c < 4; c++)
            win[r * 4 + c] = sx[((py0 + r) * 18 + px0 + c) * XS + c4];

#pragma unroll
        for (int ky = 0; ky < 3; ky++)
#pragma unroll
        for (int kx = 0; kx < 3; kx++) {
            const int* __restrict__ w = sw_ + ((ky * 3 + kx) * CIN4 + c4) * COUT + chbase;
#pragma unroll
            for (int j = 0; j < CO; j += 4) {
                const int4 w4 = *reinterpret_cast<const int4*>(w + j);
#pragma unroll
                for (int p = 0; p < 4; p++) {
                    const int xw = win[((p >> 1) + ky) * 4 + (p & 1) + kx];
                    acc[p][j + 0] = __dp4a(xw, w4.x, acc[p][j + 0]);
                    acc[p][j + 1] = __dp4a(xw, w4.y, acc[p][j + 1]);
                    acc[p][j + 2] = __dp4a(xw, w4.z, acc[p][j + 2]);
                    acc[p][j + 3] = __dp4a(xw, w4.w, acc[p][j + 3]);
                }
            }
        }
    }

    if (POOL) {
        const int gy = y0 + py0, gx = x0 + px0;
        if (gy < H && gx < W) {
            unsigned pk[CO / 4];
#pragma unroll
            for (int j = 0; j < CO / 4; j++) pk[j] = 0;
#pragma unroll
            for (int o = 0; o < CO; o++) {
                const int m = max(max(acc[0][o], acc[1][o]), max(acc[2][o], acc[3][o]));
                const float y = fmaf((float)m, sA[chbase + o], sB[chbase + o]);
                int qq = __float2int_rn(y);
                qq = min(15, max(0, qq));
                pk[o >> 2] |= (unsigned)slut[qq] << ((o & 3) * 8);
            }
            unsigned char* dst = out
                + ((size_t)(b * (H >> 1) + (gy >> 1)) * (W >> 1) + (gx >> 1)) * COUT + chbase;
            if constexpr (CO == 16)
                *reinterpret_cast<uint4*>(dst) = make_uint4(pk[0], pk[1], pk[2], pk[3]);
            else if constexpr (CO == 8)
                *reinterpret_cast<uint2*>(dst) = make_uint2(pk[0], pk[1]);
            else
                *reinterpret_cast<unsigned*>(dst) = pk[0];
        }
    } else {
#pragma unroll
        for (int p = 0; p < 4; p++) {
            const int gy = y0 + py0 + (p >> 1), gx = x0 + px0 + (p & 1);
            if (gy < H && gx < W) {
                unsigned pk[CO / 4];
#pragma unroll
                for (int j = 0; j < CO / 4; j++) pk[j] = 0;
#pragma unroll
                for (int o = 0; o < CO; o++) {
                    const float y = fmaf((float)acc[p][o], sA[chbase + o], sB[chbase + o]);
                    int qq = __float2int_rn(y);
                    qq = min(15, max(0, qq));
                    pk[o >> 2] |= (unsigned)slut[qq] << ((o & 3) * 8);
                }
                unsigned char* dst = out + ((size_t)(b * H + gy) * W + gx) * COUT + chbase;
                if constexpr (CO == 16)
                    *reinterpret_cast<uint4*>(dst) = make_uint4(pk[0], pk[1], pk[2], pk[3]);
                else if constexpr (CO == 8)
                    *reinterpret_cast<uint2*>(dst) = make_uint2(pk[0], pk[1]);
                else
                    *reinterpret_cast<unsigned*>(dst) = pk[0];
            }
        }
    }
}

// ---------------- tensor-core conv (b2, b3): mma.sync m16n8k32 s8 ----------------
// Same fragment mapping as R15 (correctness-validated, rel_err 9e-8). Change:
// weights re-laid out at smem-fill time to stride 72 per c4 (72 mod 32 = 8), so
// B-operand lane banks are lq*8 + l4 = all 32 distinct -> conflict-free (R15's
// stride-64 layout had a 4-way conflict on every B load). A-tile strides XS=20/12
// are conflict-free as before. POOL epilogue unchanged.
#define MMA_S8(c, a0, a1, a2, a3, b0, b1)                                   \
    asm volatile("mma.sync.aligned.m16n8k32.row.col.s32.s8.s8.s32 "         \
                 "{%0,%1,%2,%3},{%4,%5,%6,%7},{%8,%9},{%0,%1,%2,%3};"       \
                 : "+r"((c)[0]), "+r"((c)[1]), "+r"((c)[2]), "+r"((c)[3])   \
                 : "r"(a0), "r"(a1), "r"(a2), "r"(a3), "r"(b0), "r"(b1))

template <int CIN4>
__global__ __launch_bounds__(256, 2) void
k_conv_mma(int inSel, int outSel, int woff, const float* __restrict__ scales,
           int sRelu, int sNext, int blk, int H, int W)
{
    constexpr int KC  = CIN4 / 8;               // k32 chunks per tap
    constexpr int XS  = (CIN4 == 16) ? 20 : 12; // pixel stride (words), conflict-free
    constexpr int CIN = CIN4 * 4;
    constexpr int NW  = 9 * CIN4 * 64;          // packed weight words
    constexpr int NWP = 9 * CIN4 * 72;          // padded smem layout (stride 72/c4)

    extern __shared__ int smem[];
    int*   sw_  = smem;                         // weights [tap][c4(stride72)][cout]
    int*   sx   = smem + NWP;                   // 18x18 halo tile
    float* sA   = (float*)(sx + 324 * XS);
    float* sB   = sA + 64;
    int*   slut = (int*)(sB + 64);
    unsigned char* stage_all = (unsigned char*)(slut + 16);  // 8 warps x 512 B

    const unsigned char* __restrict__ in  = inSel ? g_actB : g_actA;
    unsigned char*       __restrict__ out = outSel ? g_actB : g_actA;

    const int tid = threadIdx.x;
    if (tid < 16) {
        const float sp = scales[sRelu], sc = scales[sNext];
        int v = __float2int_rn(__fdiv_rn((float)tid * sp, sc));
        slut[tid] = min(7, max(-8, v)) & 255;
    }
    if (tid < 64) { sA[tid] = g_A[blk * 64 + tid]; sB[tid] = g_B[blk * 64 + tid]; }
    {   // fill with stride-72 re-layout (int4 chunks; o multiple of 4, 72c4 mult of 4)
        const int4* __restrict__ wq4 = reinterpret_cast<const int4*>(g_wq + woff);
        for (int k = tid; k < NW / 4; k += 256) {
            const int4 v = wq4[k];
            const int w0  = k * 4;
            const int tap = w0 / (CIN4 * 64);
            const int rem = w0 % (CIN4 * 64);
            const int c4  = rem >> 6, o = rem & 63;
            *reinterpret_cast<int4*>(sw_ + tap * CIN4 * 72 + c4 * 72 + o) = v;
        }
    }

    const int b  = blockIdx.z;
    const int x0 = blockIdx.x * 16, y0 = blockIdx.y * 16;

    {   // halo load (zero-filled OOB)
        constexpr int NC16 = CIN4 / 4;
        for (int i = tid; i < 324 * NC16; i += 256) {
            const int pix = i / NC16, c16 = i % NC16;
            const int ty = pix / 18, tx = pix % 18;
            const int iy = y0 + ty - 1, ix = x0 + tx - 1;
            uint4 v = make_uint4(0, 0, 0, 0);
            if (iy >= 0 && iy < H && ix >= 0 && ix < W)
                v = *reinterpret_cast<const uint4*>(
                    in + ((size_t)(b * H + iy) * W + ix) * CIN + c16 * 16);
            int* d = sx + pix * XS + c16 * 4;
            d[0] = (int)v.x; d[1] = (int)v.y; d[2] = (int)v.z; d[3] = (int)v.w;
        }
    }
    __syncthreads();

    const int wid = tid >> 5, lane = tid & 31;
    const int l4 = lane >> 2, lq = lane & 3;
    const int t0 = wid * 2;                  // warp's first tile row

    int C[2][8][4];
#pragma unroll
    for (int r = 0; r < 2; r++)
#pragma unroll
    for (int nt = 0; nt < 8; nt++)
#pragma unroll
    for (int j = 0; j < 4; j++) C[r][nt][j] = 0;

    const int pA = (t0 * 18 + l4) * XS + lq;

#pragma unroll
    for (int ky = 0; ky < 3; ky++)
#pragma unroll
    for (int kx = 0; kx < 3; kx++)
#pragma unroll
    for (int kc = 0; kc < KC; kc++) {
        const int ao = pA + (ky * 18 + kx) * XS + kc * 8;
        const int a00 = sx[ao];
        const int a01 = sx[ao + 8 * XS];
        const int a02 = sx[ao + 4];
        const int a03 = sx[ao + 8 * XS + 4];
        const int a10 = sx[ao + 18 * XS];
        const int a11 = sx[ao + 26 * XS];
        const int a12 = sx[ao + 18 * XS + 4];
        const int a13 = sx[ao + 26 * XS + 4];
        // B: c4 = kc*8 + lq (+4 for hi half); stride 72 -> conflict-free
        const int bo = ((ky * 3 + kx) * CIN4 + kc * 8 + lq) * 72 + l4;
#pragma unroll
        for (int nt = 0; nt < 8; nt++) {
            const int b0 = sw_[bo + nt * 8];
            const int b1 = sw_[bo + 288 + nt * 8];   // +4*72
            MMA_S8(C[0][nt], a00, a01, a02, a03, b0, b1);
            MMA_S8(C[1][nt], a10, a11, a12, a13, b0, b1);
        }
    }

    unsigned char* stage = stage_all + wid * 512;

#pragma unroll
    for (int nt = 0; nt < 8; nt++) {
        int m0 = max(C[0][nt][0], C[1][nt][0]);
        int m1 = max(C[0][nt][1], C[1][nt][1]);
        int m2 = max(C[0][nt][2], C[1][nt][2]);
        int m3 = max(C[0][nt][3], C[1][nt][3]);
        m0 = max(m0, __shfl_xor_sync(0xffffffffu, m0, 4));
        m1 = max(m1, __shfl_xor_sync(0xffffffffu, m1, 4));
        m2 = max(m2, __shfl_xor_sync(0xffffffffu, m2, 4));
        m3 = max(m3, __shfl_xor_sync(0xffffffffu, m3, 4));
        if ((l4 & 1) == 0) {
            const int co = nt * 8 + lq * 2;
            int q0 = __float2int_rn(fmaf((float)m0, sA[co], sB[co]));
            int q1 = __float2int_rn(fmaf((float)m1, sA[co + 1], sB[co + 1]));
            int q2 = __float2int_rn(fmaf((float)m2, sA[co], sB[co]));
            int q3 = __float2int_rn(fmaf((float)m3, sA[co + 1], sB[co + 1]));
            q0 = min(15, max(0, q0)); q1 = min(15, max(0, q1));
            q2 = min(15, max(0, q2)); q3 = min(15, max(0, q3));
            *(unsigned short*)(stage + (l4 >> 1) * 64 + co) =
                (unsigned short)(slut[q0] | (slut[q1] << 8));
            *(unsigned short*)(stage + (4 + (l4 >> 1)) * 64 + co) =
                (unsigned short)(slut[q2] | (slut[q3] << 8));
        }
    }
    __syncwarp();
    const int Ho = H >> 1, Wo = W >> 1;
    const int oy = (y0 >> 1) + wid;
    const int ox = (x0 >> 1) + l4;
    if (oy < Ho && ox < Wo) {
        const uint4 v = *(const uint4*)(stage + l4 * 64 + lq * 16);
        *(uint4*)(out + ((size_t)(b * Ho + oy) * Wo + ox) * 64 + lq * 16) = v;
    }
}

// ---------------- head: 1x1 conv (64->36) + bias, fp32 NCHW out ----------------
__global__ __launch_bounds__(256) void
k_head(float* __restrict__ outp, const float* __restrict__ b9)
{
    __shared__ int   sw_[576];
    __shared__ float s_sc;
    const int tid = threadIdx.x;
    if (tid == 0) s_sc = g_head_sc;
    for (int i = tid; i < 576; i += 256) sw_[i] = g_wq[51984 + i];
    __syncthreads();

    const int p = blockIdx.x * 256 + tid;
    if (p >= 12800) return;
    const int b = p / 800, rem = p % 800;
    const int4* __restrict__ src = reinterpret_cast<const int4*>(g_actB + (size_t)p * 64);

    int xw[16];
#pragma unroll
    for (int j = 0; j < 4; j++) {
        const int4 v = src[j];
        xw[4 * j + 0] = v.x; xw[4 * j + 1] = v.y; xw[4 * j + 2] = v.z; xw[4 * j + 3] = v.w;
    }
    int acc[36];
#pragma unroll
    for (int o = 0; o < 36; o++) acc[o] = 0;
#pragma unroll
    for (int c4 = 0; c4 < 16; c4++) {
        const int x = xw[c4];
        const int* __restrict__ w = sw_ + c4 * 36;
#pragma unroll
        for (int o = 0; o < 36; o++) acc[o] = __dp4a(x, w[o], acc[o]);
    }
    const float sc = s_sc;
#pragma unroll
    for (int o = 0; o < 36; o++)
        outp[(size_t)(b * 36 + o) * 800 + rem] = (float)acc[o] * sc + __ldg(&b9[o]);
}

// ---------------- launch ----------------
extern "C" void kernel_launch(void* const* d_in, const int* in_sizes, int n_in,
                              void* d_out, int out_size)
{
    const float* x      = (const float*)d_in[0];
    const float* b9     = (const float*)d_in[10];
    const float* scales = (const float*)d_in[19];

    const int wn[9] = {432, 4608, 18432, 36864, 36864, 36864, 36864, 36864, 2304};

    MaxArgs ma;
    for (int i = 0; i < 9; i++) { ma.p[i] = (const float*)d_in[1 + i]; ma.n[i] = wn[i]; }
    k_maxabs<<<9, 256>>>(ma);

    PackArgs pa;
    for (int i = 0; i < 9; i++) pa.w[i] = (const float*)d_in[1 + i];
    k_pack<<<(52560 + 255) / 256, 256>>>(pa);

    BnArgs ba;
    for (int i = 0; i < 8; i++) ba.bn[i] = (const float*)d_in[11 + i];
    ba.scales = scales;
    k_params<<<1, 256>>>(ba);

    // mma b3 smem: (9*16*72 + 324*20 + 128 + 16)*4 + 8*512 = 72064 B (>48K)
    cudaFuncSetAttribute(k_conv_mma<16>, cudaFuncAttributeMaxDynamicSharedMemorySize, 72064);

    //                                   grid                smem       in out  woff           sRelu sNext blk  H    W
    k_conv<1, 16, true, 2, true, 4><<<dim3(40, 10, 16), 256,  3280>>>(x, 0, 0,     0, scales, 10, 2, 0, 320, 640);
    k_conv<4, 32, true, 4, false,4><<<dim3(20, 10, 16), 256, 11472>>>(x, 0, 1,   144, scales, 11, 3, 1, 160, 320);
    // b2 mma smem: (9*8*72 + 324*12 + 128 + 16)*4 + 4096 = 40960 B
    k_conv_mma<8 ><<<dim3(10, 5, 16), 256, 40960>>>(1, 0,  1296, scales, 12, 4, 2,  80, 160);
    k_conv_mma<16><<<dim3( 5, 3, 16), 256, 72064>>>(0, 1,  5904, scales, 13, 5, 3,  40,  80);
    k_conv<16, 64, false, 16, false, 4><<<dim3(3, 5, 16), 256, 44848>>>(x, 1, 0, 15120, scales, 14, 6, 4, 20, 40);
    k_conv<16, 64, false, 16, false, 4><<<dim3(3, 5, 16), 256, 44848>>>(x, 0, 1, 24336, scales, 15, 7, 5, 20, 40);
    k_conv<16, 64, false, 16, false, 4><<<dim3(3, 5, 16), 256, 44848>>>(x, 1, 0, 33552, scales, 16, 8, 6, 20, 40);
    k_conv<16, 64, false, 16, false, 4><<<dim3(3, 5, 16), 256, 44848>>>(x, 0, 1, 42768, scales, 17, 9, 7, 20, 40);
    k_head<<<50, 256>>>((float*)d_out, b9);
}

// round 17
// speedup vs baseline: 1.2343x; 1.0841x over previous
#include <cuda_runtime.h>

#define EPSB 1e-5f
#define NB 16

// ---------------- device-global scratch (no allocation allowed) ----------------
__device__ __align__(128) unsigned char g_actA[NB * 160 * 320 * 16]; // 13.1 MB
__device__ __align__(128) unsigned char g_actB[NB * 80 * 160 * 32];  //  6.6 MB

// packed int8x4 quantized weights, layout per weight: [tap][cin4][cout]
__device__ int   g_wq[52560];
__device__ float g_sw[9];
__device__ float g_A[512];
__device__ float g_B[512];
__device__ float g_head_sc;

// ---------------- prep kernels ----------------
struct MaxArgs { const float* p[9]; int n[9]; };

__global__ void k_maxabs(MaxArgs a) {
    __shared__ float red[8];
    const int b = blockIdx.x;
    const float* __restrict__ w = a.p[b];
    const int n = a.n[b];
    float m = 0.f;
    for (int i = threadIdx.x; i < n; i += blockDim.x) m = fmaxf(m, fabsf(w[i]));
    for (int s = 16; s; s >>= 1) m = fmaxf(m, __shfl_xor_sync(0xffffffffu, m, s));
    if ((threadIdx.x & 31) == 0) red[threadIdx.x >> 5] = m;
    __syncthreads();
    if (threadIdx.x < 32) {
        float v = (threadIdx.x < 8) ? red[threadIdx.x] : 0.f;
        for (int s = 4; s; s >>= 1) v = fmaxf(v, __shfl_xor_sync(0xffffffffu, v, s));
        if (threadIdx.x == 0) g_sw[b] = v / 7.0f;
    }
}

// pack weights + compute epilogue params in ONE kernel (both depend only on g_sw)
struct PrepArgs { const float* w[9]; const float* bn[8]; const float* scales; };

__global__ void k_prep(PrepArgs a) {
    const int off[10]  = {0, 144, 1296, 5904, 15120, 24336, 33552, 42768, 51984, 52560};
    const int cinR[9]  = {3, 16, 32, 64, 64, 64, 64, 64, 64};
    const int cin4[9]  = {1, 4, 8, 16, 16, 16, 16, 16, 16};
    const int coutA[9] = {16, 32, 64, 64, 64, 64, 64, 64, 36};
    const int kk[9]    = {3, 3, 3, 3, 3, 3, 3, 3, 1};
    const int couts[8] = {16, 32, 64, 64, 64, 64, 64, 64};

    int idx = blockIdx.x * blockDim.x + threadIdx.x;
    if (idx < 52560) {
        int wi = 0;
        while (wi < 8 && idx >= off[wi + 1]) wi++;
        const int local = idx - off[wi];
        const int C4 = cin4[wi], CO = coutA[wi], K = kk[wi], CR = cinR[wi];
        const int tap = local / (C4 * CO);
        const int rest = local % (C4 * CO);
        const int c4 = rest / CO, o = rest % CO;
        const int ky = tap / K, kx = tap % K;
        const float s = g_sw[wi];
        const float* __restrict__ w = a.w[wi];
        unsigned packed = 0;
#pragma unroll
        for (int j = 0; j < 4; j++) {
            const int ci = c4 * 4 + j;
            int q = 0;
            if (ci < CR) {
                float v = w[((o * CR + ci) * K + ky) * K + kx];
                q = __float2int_rn(__fdiv_rn(v, s));
                q = min(7, max(-7, q));
            }
            packed |= (unsigned)(q & 255) << (j * 8);
        }
        g_wq[idx] = (int)packed;
    } else if (idx < 53072) {
        const int i = idx - 52560;          // 0..511
        const int blk = i >> 6, c = i & 63;
        const int C = couts[blk];
        if (c < C) {
            const float* __restrict__ bn = a.bn[blk];
            const float g = bn[c], b = bn[C + c], m = bn[2 * C + c], v = bn[3 * C + c];
            const float inv = __fdiv_rn(g, sqrtf(v + EPSB));
            const float s_in = a.scales[1 + blk];
            const float s_relu = a.scales[10 + blk];
            const float sw = g_sw[blk];
            g_A[i] = __fdiv_rn(sw * s_in * inv, s_relu);
            g_B[i] = __fdiv_rn(b - m * inv, s_relu);
        }
    } else if (idx == 53072) {
        g_head_sc = g_sw[8] * a.scales[9];
    }
}

// ---------------- generic fused conv block (dp4a, R14-proven) ----------------
// CHG-way channel split: 256 threads = CHG groups x NQ quads.
//   CHG=2: 16x32 tile; CHG=4: 16x16; CHG=8: 16x8; CHG=16: 16x4.
// chgrp warp-uniform for CHG<=8 (weight LDS.128 = full warp broadcast); CHG=16
// is 2-addr/warp (accepted for occupancy on tiny late layers). 4x4 window in
// regs per c4. In-thread 2x2 pooling. Interior CTAs take an unguarded halo path.
// MINB: __launch_bounds__ min-blocks (4 -> 64-reg cap; 5 -> 51-reg cap).
// FIRST: halo loader reads fp32 NCHW input, quantizes via rcp-mul + lut01.
// Epilogue: BN -> clamp q15 -> producer-side LUT to next block's input code.
template <int CIN4, int COUT, bool POOL, int CHG, bool FIRST, int MINB>
__global__ __launch_bounds__(256, MINB) void
k_conv(const float* __restrict__ xin, int inSel, int outSel, int woff,
       const float* __restrict__ scales, int sRelu, int sNext, int blk, int H, int W)
{
    constexpr int NQ   = 256 / CHG;
    constexpr int CO   = COUT / CHG;
    constexpr int TH   = (NQ / 8) * 2;
    constexpr int HR   = TH + 2;
    constexpr int CIN  = CIN4 * 4;
    constexpr int XS   = CIN4 | 1;
    constexpr int NW   = 9 * CIN4 * COUT;

    extern __shared__ int smem[];
    int*   sw_   = smem;
    int*   sx    = smem + NW;
    float* sA    = (float*)(sx + HR * 18 * XS);
    float* sB    = sA + COUT;
    int*   slut  = (int*)(sB + COUT);
    int*   lut01 = slut + 16;

    const unsigned char* __restrict__ in  = inSel ? g_actB : g_actA;
    unsigned char*       __restrict__ out = outSel ? g_actB : g_actA;

    const int tid = threadIdx.x;
    if (tid < 16) {
        const float sp = scales[sRelu], sc = scales[sNext];
        int v = __float2int_rn(__fdiv_rn((float)tid * sp, sc));
        slut[tid] = min(7, max(-8, v)) & 255;
        if (FIRST) {
            int u = __float2int_rn(__fdiv_rn((float)(tid - 8) * scales[0], scales[1]));
            lut01[tid] = min(7, max(-8, u)) & 255;
        }
    }
    if (tid < COUT) { sA[tid] = g_A[blk * 64 + tid]; sB[tid] = g_B[blk * 64 + tid]; }
    {
        const int4* __restrict__ wq4 = reinterpret_cast<const int4*>(g_wq + woff);
        int4* sw4 = reinterpret_cast<int4*>(sw_);
        for (int i = tid; i < NW / 4; i += 256) sw4[i] = wq4[i];
    }

    const int b  = blockIdx.z;
    const int x0 = blockIdx.x * 16, y0 = blockIdx.y * TH;
    const bool interior = (x0 > 0) && (x0 + 17 <= W) && (y0 > 0) && (y0 + TH + 1 <= H);

    if constexpr (FIRST) {
        __syncthreads();                    // halo below reads lut01 (smem)
        const float r0 = __frcp_rn(__ldg(&scales[0]));
        if (interior) {
            for (int i = tid; i < HR * 18; i += 256) {
                const int ty = i / 18, tx = i % 18;
                const size_t base = (size_t)b * 3 * H * W
                                  + (size_t)(y0 + ty - 1) * W + (x0 + tx - 1);
                unsigned pkd = 0;
#pragma unroll
                for (int c = 0; c < 3; c++) {
                    const float f = xin[base + (size_t)c * H * W];
                    int q0 = __float2int_rn(f * r0);
                    q0 = min(7, max(-8, q0));
                    pkd |= (unsigned)lut01[q0 + 8] << (8 * c);
                }
                sx[i * XS] = (int)pkd;
            }
        } else {
            for (int i = tid; i < HR * 18; i += 256) {
                const int ty = i / 18, tx = i % 18;
                const int iy = y0 + ty - 1, ix = x0 + tx - 1;
                unsigned pkd = 0;
                if (iy >= 0 && iy < H && ix >= 0 && ix < W) {
                    const size_t base = (size_t)b * 3 * H * W + (size_t)iy * W + ix;
#pragma unroll
                    for (int c = 0; c < 3; c++) {
                        const float f = xin[base + (size_t)c * H * W];
                        int q0 = __float2int_rn(f * r0);
                        q0 = min(7, max(-8, q0));
                        pkd |= (unsigned)lut01[q0 + 8] << (8 * c);
                    }
                }
                sx[i * XS] = (int)pkd;
            }
        }
    } else if constexpr (CIN4 >= 4) {
        constexpr int NC16 = CIN4 / 4;
        if (interior) {
            for (int i = tid; i < HR * 18 * NC16; i += 256) {
                const int pix = i / NC16, c16 = i % NC16;
                const int ty = pix / 18, tx = pix % 18;
                const uint4 v = *reinterpret_cast<const uint4*>(
                    in + ((size_t)(b * H + y0 + ty - 1) * W + (x0 + tx - 1)) * CIN + c16 * 16);
                int* d = sx + pix * XS + c16 * 4;
                d[0] = (int)v.x; d[1] = (int)v.y; d[2] = (int)v.z; d[3] = (int)v.w;
            }
        } else {
            for (int i = tid; i < HR * 18 * NC16; i += 256) {
                const int pix = i / NC16, c16 = i % NC16;
                const int ty = pix / 18, tx = pix % 18;
                const int iy = y0 + ty - 1, ix = x0 + tx - 1;
                uint4 v = make_uint4(0, 0, 0, 0);
                if (iy >= 0 && iy < H && ix >= 0 && ix < W)
                    v = *reinterpret_cast<const uint4*>(
                        in + ((size_t)(b * H + iy) * W + ix) * CIN + c16 * 16);
                int* d = sx + pix * XS + c16 * 4;
                d[0] = (int)v.x; d[1] = (int)v.y; d[2] = (int)v.z; d[3] = (int)v.w;
            }
        }
    } else {
        for (int i = tid; i < HR * 18; i += 256) {
            const int ty = i / 18, tx = i % 18;
            const int iy = y0 + ty - 1, ix = x0 + tx - 1;
            int v = 0;
            if (iy >= 0 && iy < H && ix >= 0 && ix < W)
                v = *reinterpret_cast<const int*>(
                    in + ((size_t)(b * H + iy) * W + ix) * 4);
            sx[i * XS] = v;
        }
    }
    __syncthreads();

    const int chgrp = tid / NQ, q = tid % NQ;
    const int chbase = chgrp * CO;
    const int px0 = (q & 7) * 2, py0 = (q >> 3) * 2;

    int acc[4][CO];
#pragma unroll
    for (int p = 0; p < 4; p++)
#pragma unroll
    for (int o = 0; o < CO; o++) acc[p][o] = 0;

    for (int c4 = 0; c4 < CIN4; c4++) {
        int win[16];
#pragma unroll
        for (int r = 0; r < 4; r++)
#pragma unroll
        for (int c = 0; c < 4; c++)
            win[r * 4 + c] = sx[((py0 + r) * 18 + px0 + c) * XS + c4];

#pragma unroll
        for (int ky = 0; ky < 3; ky++)
#pragma unroll
        for (int kx = 0; kx < 3; kx++) {
            const int* __restrict__ w = sw_ + ((ky * 3 + kx) * CIN4 + c4) * COUT + chbase;
#pragma unroll
            for (int j = 0; j < CO; j += 4) {
                const int4 w4 = *reinterpret_cast<const int4*>(w + j);
#pragma unroll
                for (int p = 0; p < 4; p++) {
                    const int xw = win[((p >> 1) + ky) * 4 + (p & 1) + kx];
                    acc[p][j + 0] = __dp4a(xw, w4.x, acc[p][j + 0]);
                    acc[p][j + 1] = __dp4a(xw, w4.y, acc[p][j + 1]);
                    acc[p][j + 2] = __dp4a(xw, w4.z, acc[p][j + 2]);
                    acc[p][j + 3] = __dp4a(xw, w4.w, acc[p][j + 3]);
                }
            }
        }
    }

    if (POOL) {
        const int gy = y0 + py0, gx = x0 + px0;
        if (gy < H && gx < W) {
            unsigned pk[CO / 4];
#pragma unroll
            for (int j = 0; j < CO / 4; j++) pk[j] = 0;
#pragma unroll
            for (int o = 0; o < CO; o++) {
                const int m = max(max(acc[0][o], acc[1][o]), max(acc[2][o], acc[3][o]));
                const float y = fmaf((float)m, sA[chbase + o], sB[chbase + o]);
                int qq = __float2int_rn(y);
                qq = min(15, max(0, qq));
                pk[o >> 2] |= (unsigned)slut[qq] << ((o & 3) * 8);
            }
            unsigned char* dst = out
                + ((size_t)(b * (H >> 1) + (gy >> 1)) * (W >> 1) + (gx >> 1)) * COUT + chbase;
            if constexpr (CO == 16)
                *reinterpret_cast<uint4*>(dst) = make_uint4(pk[0], pk[1], pk[2], pk[3]);
            else if constexpr (CO == 8)
                *reinterpret_cast<uint2*>(dst) = make_uint2(pk[0], pk[1]);
            else
                *reinterpret_cast<unsigned*>(dst) = pk[0];
        }
    } else {
#pragma unroll
        for (int p = 0; p < 4; p++) {
            const int gy = y0 + py0 + (p >> 1), gx = x0 + px0 + (p & 1);
            if (gy < H && gx < W) {
                unsigned pk[CO / 4];
#pragma unroll
                for (int j = 0; j < CO / 4; j++) pk[j] = 0;
#pragma unroll
                for (int o = 0; o < CO; o++) {
                    const float y = fmaf((float)acc[p][o], sA[chbase + o], sB[chbase + o]);
                    int qq = __float2int_rn(y);
                    qq = min(15, max(0, qq));
                    pk[o >> 2] |= (unsigned)slut[qq] << ((o & 3) * 8);
                }
                unsigned char* dst = out + ((size_t)(b * H + gy) * W + gx) * COUT + chbase;
                if constexpr (CO == 16)
                    *reinterpret_cast<uint4*>(dst) = make_uint4(pk[0], pk[1], pk[2], pk[3]);
                else if constexpr (CO == 8)
                    *reinterpret_cast<uint2*>(dst) = make_uint2(pk[0], pk[1]);
                else
                    *reinterpret_cast<unsigned*>(dst) = pk[0];
            }
        }
    }
}

// ---------------- head: 1x1 conv (64->36) + bias, fp32 NCHW out ----------------
__global__ __launch_bounds__(256) void
k_head(float* __restrict__ outp, const float* __restrict__ b9)
{
    __shared__ int   sw_[576];
    __shared__ float s_sc;
    const int tid = threadIdx.x;
    if (tid == 0) s_sc = g_head_sc;
    for (int i = tid; i < 576; i += 256) sw_[i] = g_wq[51984 + i];
    __syncthreads();

    const int p = blockIdx.x * 256 + tid;
    if (p >= 12800) return;
    const int b = p / 800, rem = p % 800;
    const int4* __restrict__ src = reinterpret_cast<const int4*>(g_actB + (size_t)p * 64);

    int xw[16];
#pragma unroll
    for (int j = 0; j < 4; j++) {
        const int4 v = src[j];
        xw[4 * j + 0] = v.x; xw[4 * j + 1] = v.y; xw[4 * j + 2] = v.z; xw[4 * j + 3] = v.w;
    }
    int acc[36];
#pragma unroll
    for (int o = 0; o < 36; o++) acc[o] = 0;
#pragma unroll
    for (int c4 = 0; c4 < 16; c4++) {
        const int x = xw[c4];
        const int* __restrict__ w = sw_ + c4 * 36;
#pragma unroll
        for (int o = 0; o < 36; o++) acc[o] = __dp4a(x, w[o], acc[o]);
    }
    const float sc = s_sc;
#pragma unroll
    for (int o = 0; o < 36; o++)
        outp[(size_t)(b * 36 + o) * 800 + rem] = (float)acc[o] * sc + __ldg(&b9[o]);
}

// ---------------- launch ----------------
extern "C" void kernel_launch(void* const* d_in, const int* in_sizes, int n_in,
                              void* d_out, int out_size)
{
    const float* x      = (const float*)d_in[0];
    const float* b9     = (const float*)d_in[10];
    const float* scales = (const float*)d_in[19];

    const int wn[9] = {432, 4608, 18432, 36864, 36864, 36864, 36864, 36864, 2304};

    MaxArgs ma;
    for (int i = 0; i < 9; i++) { ma.p[i] = (const float*)d_in[1 + i]; ma.n[i] = wn[i]; }
    k_maxabs<<<9, 256>>>(ma);

    PrepArgs pr;
    for (int i = 0; i < 9; i++) pr.w[i] = (const float*)d_in[1 + i];
    for (int i = 0; i < 8; i++) pr.bn[i] = (const float*)d_in[11 + i];
    pr.scales = scales;
    k_prep<<<208, 256>>>(pr);

    // smem bytes = 4*(NW + HR*18*XS + 2*COUT + 32); all instances < 48KB.
    //                                   grid                smem      in out  woff           sRelu sNext blk  H    W
    k_conv<1,  16, true,  2, true, 4><<<dim3(40, 10, 16), 256,  3280>>>(x, 0, 0,     0, scales, 10, 2, 0, 320, 640);
    k_conv<4,  32, true,  4, false,4><<<dim3(20, 10, 16), 256, 11472>>>(x, 0, 1,   144, scales, 11, 3, 1, 160, 320);
    k_conv<8,  64, true,  8, false,4><<<dim3(10, 10, 16), 256, 25552>>>(x, 1, 0,  1296, scales, 12, 4, 2,  80, 160);
    k_conv<16, 64, true, 16, false,5><<<dim3( 5, 10, 16), 256, 44848>>>(x, 0, 1,  5904, scales, 13, 5, 3,  40,  80);
    k_conv<16, 64, false,16, false,5><<<dim3( 3,  5, 16), 256, 44848>>>(x, 1, 0, 15120, scales, 14, 6, 4,  20,  40);
    k_conv<16, 64, false,16, false,5><<<dim3( 3,  5, 16), 256, 44848>>>(x, 0, 1, 24336, scales, 15, 7, 5,  20,  40);
    k_conv<16, 64, false,16, false,5><<<dim3( 3,  5, 16), 256, 44848>>>(x, 1, 0, 33552, scales, 16, 8, 6,  20,  40);
    k_conv<16, 64, false,16, false,5><<<dim3( 3,  5, 16), 256, 44848>>>(x, 0, 1, 42768, scales, 17, 9, 7,  20,  40);
    k_head<<<50, 256>>>((float*)d_out, b9);
}